// round 2
// baseline (speedup 1.0000x reference)
#include <cuda_runtime.h>

// Problem constants
#define BB 128   // batch
#define TT 128   // timesteps
#define NN 100   // subactors
#define HH 16    // hidden
#define SS 6     // state
#define GG 48    // 3*H gates

typedef unsigned long long ull;

// ---- packed f32x2 helpers (sm_100+; ptxas never auto-fuses these) ----
__device__ __forceinline__ ull ffma2(ull a, ull b, ull c) {
    ull d; asm("fma.rn.f32x2 %0, %1, %2, %3;" : "=l"(d) : "l"(a), "l"(b), "l"(c)); return d;
}
__device__ __forceinline__ ull pack2(float lo, float hi) {
    ull r; asm("mov.b64 %0, {%1, %2};" : "=l"(r) : "f"(lo), "f"(hi)); return r;
}
__device__ __forceinline__ float2 unpack2(ull v) {
    float2 f; asm("mov.b64 {%0, %1}, %2;" : "=f"(f.x), "=f"(f.y) : "l"(v)); return f;
}
// ---- fast activations (MUFU-based, ~1e-6 rel err) ----
__device__ __forceinline__ float fex2(float x) { float y; asm("ex2.approx.f32 %0, %1;" : "=f"(y) : "f"(x)); return y; }
__device__ __forceinline__ float frcp(float x) { float y; asm("rcp.approx.f32 %0, %1;" : "=f"(y) : "f"(x)); return y; }
__device__ __forceinline__ float fsigmoid(float x) {
    return frcp(1.0f + fex2(-1.4426950408889634f * x));   // saturates via inf/0
}
__device__ __forceinline__ float ftanh_(float x) {
    return fmaf(-2.0f, frcp(1.0f + fex2(2.8853900817779268f * x)), 1.0f);
}

// Shared weight layouts, all packed as f32x2 (ull), 16B-aligned for LDS.128.
// Gate pairing: gates 0..31 are r(16) then z(16): pair p in [0,16) = gates (2p, 2p+1).
// n-gates 32..47: pair p in [0,8) = gates (32+2p, 33+2p).
struct __align__(16) SmemW {
    ull whh_rz[HH][16];   // [k][pair]  r/z gates, h weights
    ull wih_rz[SS][16];   // [k][pair]  r/z gates, x weights
    ull whh_n [HH][8];    // [k][pair]  n gates, h weights
    ull wih_n [SS][8];    // [k][pair]  n gates, x weights
    ull b_rz[16];         // bih+bhh fused
    ull b_xn[8];          // bih (n gates)
    ull b_hn[8];          // bhh (n gates)
    ull w1[HH][8];        // [k][pair over outputs]
    ull w2[HH][8];
    ull w3[8];            // K-packed pairs
    ull b1[8], b2[8];
    float b3;
};

__global__ void __launch_bounds__(BB)
actor_fused_kernel(const float* __restrict__ x,
                   const float* __restrict__ Wih, const float* __restrict__ Whh,
                   const float* __restrict__ bih, const float* __restrict__ bhh,
                   const float* __restrict__ W1,  const float* __restrict__ b1,
                   const float* __restrict__ W2,  const float* __restrict__ b2,
                   const float* __restrict__ W3,  const float* __restrict__ b3,
                   float* __restrict__ out)
{
    __shared__ SmemW sw;
    const int n   = blockIdx.x;
    const int tid = threadIdx.x;
    const int b   = threadIdx.x;

    // ---------------- one-time weight staging ----------------
    const float* WhhN = Whh + n * GG * HH;
    const float* WihN = Wih + n * GG * SS;
    // whh_rz: 16k x 16p = 256
    for (int i = tid; i < HH * 16; i += BB) {
        int k = i >> 4, p = i & 15;
        sw.whh_rz[k][p] = pack2(WhhN[(2 * p) * HH + k], WhhN[(2 * p + 1) * HH + k]);
    }
    // whh_n: 16k x 8p = 128
    for (int i = tid; i < HH * 8; i += BB) {
        int k = i >> 3, p = i & 7;
        sw.whh_n[k][p] = pack2(WhhN[(32 + 2 * p) * HH + k], WhhN[(33 + 2 * p) * HH + k]);
    }
    // wih_rz: 6k x 16p = 96
    for (int i = tid; i < SS * 16; i += BB) {
        int k = i >> 4, p = i & 15;
        sw.wih_rz[k][p] = pack2(WihN[(2 * p) * SS + k], WihN[(2 * p + 1) * SS + k]);
    }
    // wih_n: 6k x 8p = 48
    for (int i = tid; i < SS * 8; i += BB) {
        int k = i >> 3, p = i & 7;
        sw.wih_n[k][p] = pack2(WihN[(32 + 2 * p) * SS + k], WihN[(33 + 2 * p) * SS + k]);
    }
    // biases
    if (tid < 16)
        sw.b_rz[tid] = pack2(bih[n * GG + 2 * tid] + bhh[n * GG + 2 * tid],
                             bih[n * GG + 2 * tid + 1] + bhh[n * GG + 2 * tid + 1]);
    else if (tid < 24) {
        int p = tid - 16;
        sw.b_xn[p] = pack2(bih[n * GG + 32 + 2 * p], bih[n * GG + 33 + 2 * p]);
        sw.b_hn[p] = pack2(bhh[n * GG + 32 + 2 * p], bhh[n * GG + 33 + 2 * p]);
    }
    // MLP
    for (int i = tid; i < HH * 8; i += BB) {
        int k = i >> 3, p = i & 7;
        sw.w1[k][p] = pack2(W1[(n * HH + 2 * p) * HH + k], W1[(n * HH + 2 * p + 1) * HH + k]);
        sw.w2[k][p] = pack2(W2[(n * HH + 2 * p) * HH + k], W2[(n * HH + 2 * p + 1) * HH + k]);
    }
    if (tid < 8) {
        sw.w3[tid] = pack2(W3[n * HH + 2 * tid], W3[n * HH + 2 * tid + 1]);
        sw.b1[tid] = pack2(b1[n * HH + 2 * tid], b1[n * HH + 2 * tid + 1]);
        sw.b2[tid] = pack2(b2[n * HH + 2 * tid], b2[n * HH + 2 * tid + 1]);
    }
    if (tid == 0) sw.b3 = b3[n];
    __syncthreads();

    // ---------------- recurrence ----------------
    ull hd[HH];                      // duplicated hidden state {h,h}
#pragma unroll
    for (int j = 0; j < HH; j++) hd[j] = 0ULL;

    const int xstride = NN * SS;
    const float* xp = x + (long long)b * TT * xstride + n * SS;
    float* op = out + n * (BB * TT) + b * TT;
    float ybuf[4];

    // prefetch t=0
    float2 nx0 = *reinterpret_cast<const float2*>(xp);
    float2 nx1 = *reinterpret_cast<const float2*>(xp + 2);
    float2 nx2 = *reinterpret_cast<const float2*>(xp + 4);

#pragma unroll 1
    for (int t = 0; t < TT; t++) {
        float2 xv0 = nx0, xv1 = nx1, xv2 = nx2;
        // prefetch next step (clamped at the end to stay in-bounds)
        const float* xq = xp + ((t + 1 < TT) ? xstride : 0);
        nx0 = *reinterpret_cast<const float2*>(xq);
        nx1 = *reinterpret_cast<const float2*>(xq + 2);
        nx2 = *reinterpret_cast<const float2*>(xq + 4);
        xp = xq;

        // --- gate accumulators (biases folded) ---
        ull rz[16], an[8], hn[8];
        {
            const ulonglong2* br = reinterpret_cast<const ulonglong2*>(sw.b_rz);
#pragma unroll
            for (int q = 0; q < 8; q++) { ulonglong2 v = br[q]; rz[2 * q] = v.x; rz[2 * q + 1] = v.y; }
            const ulonglong2* bx = reinterpret_cast<const ulonglong2*>(sw.b_xn);
            const ulonglong2* bh = reinterpret_cast<const ulonglong2*>(sw.b_hn);
#pragma unroll
            for (int q = 0; q < 4; q++) {
                ulonglong2 v = bx[q]; an[2 * q] = v.x; an[2 * q + 1] = v.y;
                ulonglong2 w = bh[q]; hn[2 * q] = w.x; hn[2 * q + 1] = w.y;
            }
        }
        // x contribution (6 k's)
        {
            float xs[SS] = { xv0.x, xv0.y, xv1.x, xv1.y, xv2.x, xv2.y };
#pragma unroll
            for (int k = 0; k < SS; k++) {
                ull xd = pack2(xs[k], xs[k]);
                const ulonglong2* wr = reinterpret_cast<const ulonglong2*>(sw.wih_rz[k]);
#pragma unroll
                for (int q = 0; q < 8; q++) {
                    ulonglong2 w = wr[q];
                    rz[2 * q]     = ffma2(xd, w.x, rz[2 * q]);
                    rz[2 * q + 1] = ffma2(xd, w.y, rz[2 * q + 1]);
                }
                const ulonglong2* wn = reinterpret_cast<const ulonglong2*>(sw.wih_n[k]);
#pragma unroll
                for (int q = 0; q < 4; q++) {
                    ulonglong2 w = wn[q];
                    an[2 * q]     = ffma2(xd, w.x, an[2 * q]);
                    an[2 * q + 1] = ffma2(xd, w.y, an[2 * q + 1]);
                }
            }
        }
        // h contribution (16 k's)
#pragma unroll
        for (int k = 0; k < HH; k++) {
            ull hk = hd[k];
            const ulonglong2* wr = reinterpret_cast<const ulonglong2*>(sw.whh_rz[k]);
#pragma unroll
            for (int q = 0; q < 8; q++) {
                ulonglong2 w = wr[q];
                rz[2 * q]     = ffma2(hk, w.x, rz[2 * q]);
                rz[2 * q + 1] = ffma2(hk, w.y, rz[2 * q + 1]);
            }
            const ulonglong2* wn = reinterpret_cast<const ulonglong2*>(sw.whh_n[k]);
#pragma unroll
            for (int q = 0; q < 4; q++) {
                ulonglong2 w = wn[q];
                hn[2 * q]     = ffma2(hk, w.x, hn[2 * q]);
                hn[2 * q + 1] = ffma2(hk, w.y, hn[2 * q + 1]);
            }
        }

        // --- activations + state update ---
#pragma unroll
        for (int u = 0; u < 8; u++) {
            float2 rr = unpack2(rz[u]);
            float2 zz = unpack2(rz[u + 8]);
            float2 xn2 = unpack2(an[u]);
            float2 hn2 = unpack2(hn[u]);
            float r0 = fsigmoid(rr.x), r1 = fsigmoid(rr.y);
            float z0 = fsigmoid(zz.x), z1 = fsigmoid(zz.y);
            float n0 = ftanh_(fmaf(r0, hn2.x, xn2.x));
            float n1 = ftanh_(fmaf(r1, hn2.y, xn2.y));
            float h0 = unpack2(hd[2 * u]).x;
            float h1 = unpack2(hd[2 * u + 1]).x;
            h0 = fmaf(z0, h0 - n0, n0);
            h1 = fmaf(z1, h1 - n1, n1);
            hd[2 * u]     = pack2(h0, h0);
            hd[2 * u + 1] = pack2(h1, h1);
        }

        // --- MLP head ---
        ull a1[8];
        {
            const ulonglong2* bb = reinterpret_cast<const ulonglong2*>(sw.b1);
#pragma unroll
            for (int q = 0; q < 4; q++) { ulonglong2 v = bb[q]; a1[2 * q] = v.x; a1[2 * q + 1] = v.y; }
        }
#pragma unroll
        for (int k = 0; k < HH; k++) {
            ull hk = hd[k];
            const ulonglong2* w1p = reinterpret_cast<const ulonglong2*>(sw.w1[k]);
#pragma unroll
            for (int q = 0; q < 4; q++) {
                ulonglong2 w = w1p[q];
                a1[2 * q]     = ffma2(hk, w.x, a1[2 * q]);
                a1[2 * q + 1] = ffma2(hk, w.y, a1[2 * q + 1]);
            }
        }
        ull y1d[HH];
#pragma unroll
        for (int p = 0; p < 8; p++) {
            float2 v = unpack2(a1[p]);
            float va = fmaxf(v.x, 0.0f), vb = fmaxf(v.y, 0.0f);
            y1d[2 * p]     = pack2(va, va);
            y1d[2 * p + 1] = pack2(vb, vb);
        }
        ull a2[8];
        {
            const ulonglong2* bb = reinterpret_cast<const ulonglong2*>(sw.b2);
#pragma unroll
            for (int q = 0; q < 4; q++) { ulonglong2 v = bb[q]; a2[2 * q] = v.x; a2[2 * q + 1] = v.y; }
        }
#pragma unroll
        for (int k = 0; k < HH; k++) {
            ull yk = y1d[k];
            const ulonglong2* w2p = reinterpret_cast<const ulonglong2*>(sw.w2[k]);
#pragma unroll
            for (int q = 0; q < 4; q++) {
                ulonglong2 w = w2p[q];
                a2[2 * q]     = ffma2(yk, w.x, a2[2 * q]);
                a2[2 * q + 1] = ffma2(yk, w.y, a2[2 * q + 1]);
            }
        }
        // layer 3: a2 pairs are already K-pairs for the dot product
        ull acc = 0ULL;
        {
            const ulonglong2* w3p = reinterpret_cast<const ulonglong2*>(sw.w3);
#pragma unroll
            for (int q = 0; q < 4; q++) {
                ulonglong2 w = w3p[q];
                float2 v0 = unpack2(a2[2 * q]);
                float2 v1 = unpack2(a2[2 * q + 1]);
                ull r0 = pack2(fmaxf(v0.x, 0.0f), fmaxf(v0.y, 0.0f));
                ull r1 = pack2(fmaxf(v1.x, 0.0f), fmaxf(v1.y, 0.0f));
                acc = ffma2(r0, w.x, acc);
                acc = ffma2(r1, w.y, acc);
            }
        }
        float2 av = unpack2(acc);
        ybuf[t & 3] = fmaxf(av.x + av.y + sw.b3, 0.0f);
        if ((t & 3) == 3) {
            *reinterpret_cast<float4*>(op + t - 3) =
                make_float4(ybuf[0], ybuf[1], ybuf[2], ybuf[3]);
        }
    }
}

extern "C" void kernel_launch(void* const* d_in, const int* in_sizes, int n_in,
                              void* d_out, int out_size)
{
    (void)in_sizes; (void)n_in; (void)out_size;
    const float* x   = (const float*)d_in[0];
    const float* Wih = (const float*)d_in[1];
    const float* Whh = (const float*)d_in[2];
    const float* bih = (const float*)d_in[3];
    const float* bhh = (const float*)d_in[4];
    const float* W1  = (const float*)d_in[5];
    const float* b1  = (const float*)d_in[6];
    const float* W2  = (const float*)d_in[7];
    const float* b2  = (const float*)d_in[8];
    const float* W3  = (const float*)d_in[9];
    const float* b3  = (const float*)d_in[10];
    float* out = (float*)d_out;

    actor_fused_kernel<<<NN, BB>>>(x, Wih, Whh, bih, bhh, W1, b1, W2, b2, W3, b3, out);
}

// round 3
// speedup vs baseline: 7.8670x; 7.8670x over previous
#include <cuda_runtime.h>

// Problem constants
#define BB 128   // batch
#define TT 128   // timesteps
#define NN 100   // subactors
#define HH 16    // hidden
#define SS 6     // state
#define GG 48    // 3*H gates

typedef unsigned long long ull;

// ---- packed f32x2 helpers ----
__device__ __forceinline__ ull ffma2(ull a, ull b, ull c) {
    ull d; asm("fma.rn.f32x2 %0, %1, %2, %3;" : "=l"(d) : "l"(a), "l"(b), "l"(c)); return d;
}
__device__ __forceinline__ ull pack2(float lo, float hi) {
    ull r; asm("mov.b64 %0, {%1, %2};" : "=l"(r) : "f"(lo), "f"(hi)); return r;
}
__device__ __forceinline__ float2 unpack2(ull v) {
    float2 f; asm("mov.b64 {%0, %1}, %2;" : "=f"(f.x), "=f"(f.y) : "l"(v)); return f;
}
// ---- fast activations (MUFU-based, ~1e-6 rel err) ----
__device__ __forceinline__ float fex2(float x) { float y; asm("ex2.approx.f32 %0, %1;" : "=f"(y) : "f"(x)); return y; }
__device__ __forceinline__ float frcp(float x) { float y; asm("rcp.approx.f32 %0, %1;" : "=f"(y) : "f"(x)); return y; }
__device__ __forceinline__ float fsigmoid(float x) {
    return frcp(1.0f + fex2(-1.4426950408889634f * x));
}
__device__ __forceinline__ float ftanh_(float x) {
    return fmaf(-2.0f, frcp(1.0f + fex2(2.8853900817779268f * x)), 1.0f);
}

// Shared weights packed as f32x2 (ull).
// Gates 0..31 = r(16),z(16): pair p in [0,16) = gates (2p,2p+1).
// n-gates 32..47: pair p in [0,8).
struct __align__(16) SmemW {
    ull whh_rz[HH][16];
    ull wih_rz[SS][16];
    ull whh_n [HH][8];
    ull wih_n [SS][8];
    ull b_rz[16];         // bih+bhh fused (r,z)
    ull b_xn[8];          // bih (n gates)
    ull b_hn[8];          // bhh (n gates)
    ull w1[HH][8];
    ull w2[HH][8];
    ull w3[8];            // K-packed pairs
    ull b1[8], b2[8];
    float b3;
};

// width-4 gather: all[4*qq + i] comes from lane (base+qq)'s own[i]
__device__ __forceinline__ void exch4(const ull own[4], ull all[16]) {
#pragma unroll
    for (int qq = 0; qq < 4; qq++) {
#pragma unroll
        for (int i = 0; i < 4; i++)
            all[4 * qq + i] = __shfl_sync(0xFFFFFFFFu, own[i], qq, 4);
    }
}

__global__ void __launch_bounds__(128, 3)
actor_fused_kernel(const float* __restrict__ x,
                   const float* __restrict__ Wih, const float* __restrict__ Whh,
                   const float* __restrict__ bih, const float* __restrict__ bhh,
                   const float* __restrict__ W1,  const float* __restrict__ b1,
                   const float* __restrict__ W2,  const float* __restrict__ b2,
                   const float* __restrict__ W3,  const float* __restrict__ b3,
                   float* __restrict__ out)
{
    __shared__ SmemW sw;
    const int n   = blockIdx.x >> 2;      // subactor
    const int qb  = blockIdx.x & 3;       // batch quarter
    const int tid = threadIdx.x;

    // ---------------- one-time weight staging ----------------
    const float* WhhN = Whh + n * GG * HH;
    const float* WihN = Wih + n * GG * SS;
    for (int i = tid; i < HH * 16; i += 128) {
        int k = i >> 4, p = i & 15;
        sw.whh_rz[k][p] = pack2(WhhN[(2 * p) * HH + k], WhhN[(2 * p + 1) * HH + k]);
    }
    for (int i = tid; i < HH * 8; i += 128) {
        int k = i >> 3, p = i & 7;
        sw.whh_n[k][p] = pack2(WhhN[(32 + 2 * p) * HH + k], WhhN[(33 + 2 * p) * HH + k]);
    }
    for (int i = tid; i < SS * 16; i += 128) {
        int k = i >> 4, p = i & 15;
        sw.wih_rz[k][p] = pack2(WihN[(2 * p) * SS + k], WihN[(2 * p + 1) * SS + k]);
    }
    for (int i = tid; i < SS * 8; i += 128) {
        int k = i >> 3, p = i & 7;
        sw.wih_n[k][p] = pack2(WihN[(32 + 2 * p) * SS + k], WihN[(33 + 2 * p) * SS + k]);
    }
    if (tid < 16)
        sw.b_rz[tid] = pack2(bih[n * GG + 2 * tid] + bhh[n * GG + 2 * tid],
                             bih[n * GG + 2 * tid + 1] + bhh[n * GG + 2 * tid + 1]);
    else if (tid < 24) {
        int p = tid - 16;
        sw.b_xn[p] = pack2(bih[n * GG + 32 + 2 * p], bih[n * GG + 33 + 2 * p]);
        sw.b_hn[p] = pack2(bhh[n * GG + 32 + 2 * p], bhh[n * GG + 33 + 2 * p]);
    }
    for (int i = tid; i < HH * 8; i += 128) {
        int k = i >> 3, p = i & 7;
        sw.w1[k][p] = pack2(W1[(n * HH + 2 * p) * HH + k], W1[(n * HH + 2 * p + 1) * HH + k]);
        sw.w2[k][p] = pack2(W2[(n * HH + 2 * p) * HH + k], W2[(n * HH + 2 * p + 1) * HH + k]);
    }
    if (tid < 8) {
        sw.w3[tid] = pack2(W3[n * HH + 2 * tid], W3[n * HH + 2 * tid + 1]);
        sw.b1[tid] = pack2(b1[n * HH + 2 * tid], b1[n * HH + 2 * tid + 1]);
        sw.b2[tid] = pack2(b2[n * HH + 2 * tid], b2[n * HH + 2 * tid + 1]);
    }
    if (tid == 0) sw.b3 = b3[n];
    __syncthreads();

    // ---------------- thread role ----------------
    const int q = tid & 3;                // gate/output slice owner
    const int s = tid >> 2;               // sequence within block (0..31)
    const int b = qb * 32 + s;            // batch index
    const int p0 = 2 * q;                 // first owned pair (of 4-wide slice)

    ull hd[HH];                           // full duplicated hidden state
#pragma unroll
    for (int j = 0; j < HH; j++) hd[j] = 0ULL;

    const int xstride = NN * SS;
    const float* xp = x + (long long)b * TT * xstride + n * SS;
    float* op = out + n * (BB * TT) + b * TT;
    float ybuf[4];

    // prefetch t=0  (all 4 lanes of a sequence load the same 24B; L1 broadcast)
    float2 nx0 = *reinterpret_cast<const float2*>(xp);
    float2 nx1 = *reinterpret_cast<const float2*>(xp + 2);
    float2 nx2 = *reinterpret_cast<const float2*>(xp + 4);

#pragma unroll 1
    for (int t = 0; t < TT; t++) {
        float2 xv0 = nx0, xv1 = nx1, xv2 = nx2;
        const float* xq = xp + ((t + 1 < TT) ? xstride : 0);
        nx0 = *reinterpret_cast<const float2*>(xq);
        nx1 = *reinterpret_cast<const float2*>(xq + 2);
        nx2 = *reinterpret_cast<const float2*>(xq + 4);
        xp = xq;

        // --- owned gate accumulators (4 r, 4 z, 4 n gates) ---
        ull ra0, ra1, za0, za1, na0, na1, ha0, ha1;
        {
            ulonglong2 vr = *reinterpret_cast<const ulonglong2*>(&sw.b_rz[p0]);
            ulonglong2 vz = *reinterpret_cast<const ulonglong2*>(&sw.b_rz[8 + p0]);
            ulonglong2 vx = *reinterpret_cast<const ulonglong2*>(&sw.b_xn[p0]);
            ulonglong2 vh = *reinterpret_cast<const ulonglong2*>(&sw.b_hn[p0]);
            ra0 = vr.x; ra1 = vr.y; za0 = vz.x; za1 = vz.y;
            na0 = vx.x; na1 = vx.y; ha0 = vh.x; ha1 = vh.y;
        }
        // x contribution
        {
            float xs[SS] = { xv0.x, xv0.y, xv1.x, xv1.y, xv2.x, xv2.y };
#pragma unroll
            for (int k = 0; k < SS; k++) {
                ull xd = pack2(xs[k], xs[k]);
                ulonglong2 wr = *reinterpret_cast<const ulonglong2*>(&sw.wih_rz[k][p0]);
                ulonglong2 wz = *reinterpret_cast<const ulonglong2*>(&sw.wih_rz[k][8 + p0]);
                ulonglong2 wn = *reinterpret_cast<const ulonglong2*>(&sw.wih_n[k][p0]);
                ra0 = ffma2(xd, wr.x, ra0); ra1 = ffma2(xd, wr.y, ra1);
                za0 = ffma2(xd, wz.x, za0); za1 = ffma2(xd, wz.y, za1);
                na0 = ffma2(xd, wn.x, na0); na1 = ffma2(xd, wn.y, na1);
            }
        }
        // h contribution
#pragma unroll
        for (int k = 0; k < HH; k++) {
            ull hk = hd[k];
            ulonglong2 wr = *reinterpret_cast<const ulonglong2*>(&sw.whh_rz[k][p0]);
            ulonglong2 wz = *reinterpret_cast<const ulonglong2*>(&sw.whh_rz[k][8 + p0]);
            ulonglong2 wn = *reinterpret_cast<const ulonglong2*>(&sw.whh_n[k][p0]);
            ra0 = ffma2(hk, wr.x, ra0); ra1 = ffma2(hk, wr.y, ra1);
            za0 = ffma2(hk, wz.x, za0); za1 = ffma2(hk, wz.y, za1);
            ha0 = ffma2(hk, wn.x, ha0); ha1 = ffma2(hk, wn.y, ha1);
        }

        // --- activations + owned state update (indices 4q..4q+3) ---
        ull own[4];
        {
            float2 r0 = unpack2(ra0), r1 = unpack2(ra1);
            float2 z0 = unpack2(za0), z1 = unpack2(za1);
            float2 xn0 = unpack2(na0), xn1 = unpack2(na1);
            float2 hn0 = unpack2(ha0), hn1 = unpack2(ha1);
            float rr[4] = { fsigmoid(r0.x), fsigmoid(r0.y), fsigmoid(r1.x), fsigmoid(r1.y) };
            float zz[4] = { fsigmoid(z0.x), fsigmoid(z0.y), fsigmoid(z1.x), fsigmoid(z1.y) };
            float nn[4] = { ftanh_(fmaf(rr[0], hn0.x, xn0.x)),
                            ftanh_(fmaf(rr[1], hn0.y, xn0.y)),
                            ftanh_(fmaf(rr[2], hn1.x, xn1.x)),
                            ftanh_(fmaf(rr[3], hn1.y, xn1.y)) };
#pragma unroll
            for (int i = 0; i < 4; i++) {
                float hold = unpack2(hd[4 * q + i]).x;
                float hnew = fmaf(zz[i], hold - nn[i], nn[i]);
                own[i] = pack2(hnew, hnew);
            }
        }
        exch4(own, hd);   // full h for next step + MLP

        // --- MLP layer 1 (owned outputs 4q..4q+3) ---
        ull a10, a11;
        {
            ulonglong2 bb = *reinterpret_cast<const ulonglong2*>(&sw.b1[p0]);
            a10 = bb.x; a11 = bb.y;
        }
#pragma unroll
        for (int k = 0; k < HH; k++) {
            ulonglong2 w = *reinterpret_cast<const ulonglong2*>(&sw.w1[k][p0]);
            a10 = ffma2(hd[k], w.x, a10);
            a11 = ffma2(hd[k], w.y, a11);
        }
        ull y1own[4];
        {
            float2 v0 = unpack2(a10), v1 = unpack2(a11);
            float y0 = fmaxf(v0.x, 0.0f), y1 = fmaxf(v0.y, 0.0f);
            float y2 = fmaxf(v1.x, 0.0f), y3 = fmaxf(v1.y, 0.0f);
            y1own[0] = pack2(y0, y0); y1own[1] = pack2(y1, y1);
            y1own[2] = pack2(y2, y2); y1own[3] = pack2(y3, y3);
        }
        ull y1d[HH];
        exch4(y1own, y1d);

        // --- MLP layer 2 (owned outputs) ---
        ull a20, a21;
        {
            ulonglong2 bb = *reinterpret_cast<const ulonglong2*>(&sw.b2[p0]);
            a20 = bb.x; a21 = bb.y;
        }
#pragma unroll
        for (int k = 0; k < HH; k++) {
            ulonglong2 w = *reinterpret_cast<const ulonglong2*>(&sw.w2[k][p0]);
            a20 = ffma2(y1d[k], w.x, a20);
            a21 = ffma2(y1d[k], w.y, a21);
        }
        // --- layer 3 partial dot over owned 4 units ---
        float partial;
        {
            float2 v0 = unpack2(a20), v1 = unpack2(a21);
            ull kp0 = pack2(fmaxf(v0.x, 0.0f), fmaxf(v0.y, 0.0f));
            ull kp1 = pack2(fmaxf(v1.x, 0.0f), fmaxf(v1.y, 0.0f));
            ulonglong2 w3v = *reinterpret_cast<const ulonglong2*>(&sw.w3[p0]);
            ull acc = ffma2(kp0, w3v.x, 0ULL);
            acc = ffma2(kp1, w3v.y, acc);
            float2 av = unpack2(acc);
            partial = av.x + av.y;
        }
        partial += __shfl_xor_sync(0xFFFFFFFFu, partial, 1);
        partial += __shfl_xor_sync(0xFFFFFFFFu, partial, 2);

        ybuf[t & 3] = fmaxf(partial + sw.b3, 0.0f);
        if ((t & 3) == 3 && q == 0) {
            *reinterpret_cast<float4*>(op + t - 3) =
                make_float4(ybuf[0], ybuf[1], ybuf[2], ybuf[3]);
        }
    }
}

extern "C" void kernel_launch(void* const* d_in, const int* in_sizes, int n_in,
                              void* d_out, int out_size)
{
    (void)in_sizes; (void)n_in; (void)out_size;
    const float* x   = (const float*)d_in[0];
    const float* Wih = (const float*)d_in[1];
    const float* Whh = (const float*)d_in[2];
    const float* bih = (const float*)d_in[3];
    const float* bhh = (const float*)d_in[4];
    const float* W1  = (const float*)d_in[5];
    const float* b1  = (const float*)d_in[6];
    const float* W2  = (const float*)d_in[7];
    const float* b2  = (const float*)d_in[8];
    const float* W3  = (const float*)d_in[9];
    const float* b3  = (const float*)d_in[10];
    float* out = (float*)d_out;

    actor_fused_kernel<<<NN * 4, 128>>>(x, Wih, Whh, bih, bhh, W1, b1, W2, b2, W3, b3, out);
}

// round 4
// speedup vs baseline: 11.6667x; 1.4830x over previous
#include <cuda_runtime.h>

#define BB 128   // batch
#define TT 128   // timesteps
#define NN 100   // subactors
#define HH 16    // hidden
#define SS 6     // state
#define GG 48    // 3*H gates

typedef unsigned long long ull;

// ---- packed f32x2 helpers ----
__device__ __forceinline__ ull ffma2(ull a, ull b, ull c) {
    ull d; asm("fma.rn.f32x2 %0, %1, %2, %3;" : "=l"(d) : "l"(a), "l"(b), "l"(c)); return d;
}
__device__ __forceinline__ ull pack2(float lo, float hi) {
    ull r; asm("mov.b64 %0, {%1, %2};" : "=l"(r) : "f"(lo), "f"(hi)); return r;
}
__device__ __forceinline__ float2 unpack2(ull v) {
    float2 f; asm("mov.b64 {%0, %1}, %2;" : "=f"(f.x), "=f"(f.y) : "l"(v)); return f;
}
__device__ __forceinline__ float hadd2(ull v) { float2 f = unpack2(v); return f.x + f.y; }
// ---- fast activations (MUFU-based, ~1e-6 rel err) ----
__device__ __forceinline__ float fex2(float x) { float y; asm("ex2.approx.f32 %0, %1;" : "=f"(y) : "f"(x)); return y; }
__device__ __forceinline__ float frcp(float x) { float y; asm("rcp.approx.f32 %0, %1;" : "=f"(y) : "f"(x)); return y; }
__device__ __forceinline__ float fsigmoid(float x) {
    return frcp(1.0f + fex2(-1.4426950408889634f * x));
}
__device__ __forceinline__ float ftanh_(float x) {
    return fmaf(-2.0f, frcp(1.0f + fex2(2.8853900817779268f * x)), 1.0f);
}

// K-pair smem layout, lane-major in the low dimension (16B stride -> conflict-free).
// Lane l (0..7) owns: r gates {2l,2l+1}, z gates {16+2l,16+2l+1}, n gates {32+2l,32+2l+1},
// MLP outputs {2l, 2l+1}. Each ulonglong2 = (gate 2l K-pair, gate 2l+1 K-pair).
struct __align__(16) SmemW {
    ulonglong2 whr[8][8];   // [kk][lane]
    ulonglong2 whz[8][8];
    ulonglong2 whn[8][8];
    ulonglong2 wir[3][8];
    ulonglong2 wiz[3][8];
    ulonglong2 win[3][8];
    ulonglong2 w1k[8][8];
    ulonglong2 w2k[8][8];
    ulonglong2 br[8], bz[8], bxn[8], bhn[8], b1v[8], b2v[8];  // (bias,0) pairs
    ull w3v[8];
    float b3v;
};

__global__ void __launch_bounds__(64)
actor_fused_kernel(const float* __restrict__ x,
                   const float* __restrict__ Wih, const float* __restrict__ Whh,
                   const float* __restrict__ bih, const float* __restrict__ bhh,
                   const float* __restrict__ W1,  const float* __restrict__ b1,
                   const float* __restrict__ W2,  const float* __restrict__ b2,
                   const float* __restrict__ W3,  const float* __restrict__ b3,
                   float* __restrict__ out)
{
    __shared__ SmemW sw;
    const int n   = blockIdx.x >> 2;      // subactor
    const int qb  = blockIdx.x & 3;       // batch quarter
    const int tid = threadIdx.x;
    const int l   = tid & 7;              // lane within 8-lane group
    const int g   = tid >> 3;             // group (0..7)

    // ---------------- one-time weight staging ----------------
    {
        const float* Wh  = Whh + n * GG * HH;
        const float* Wi  = Wih + n * GG * SS;
        const float* W1N = W1 + n * HH * HH;
        const float* W2N = W2 + n * HH * HH;
        const int kk = tid >> 3, ll = tid & 7;      // one (kk,ll) per thread
        const int gr = 2 * ll, gz = 16 + 2 * ll, gn = 32 + 2 * ll;
        sw.whr[kk][ll] = make_ulonglong2(
            pack2(Wh[gr * HH + 2 * kk],       Wh[gr * HH + 2 * kk + 1]),
            pack2(Wh[(gr + 1) * HH + 2 * kk], Wh[(gr + 1) * HH + 2 * kk + 1]));
        sw.whz[kk][ll] = make_ulonglong2(
            pack2(Wh[gz * HH + 2 * kk],       Wh[gz * HH + 2 * kk + 1]),
            pack2(Wh[(gz + 1) * HH + 2 * kk], Wh[(gz + 1) * HH + 2 * kk + 1]));
        sw.whn[kk][ll] = make_ulonglong2(
            pack2(Wh[gn * HH + 2 * kk],       Wh[gn * HH + 2 * kk + 1]),
            pack2(Wh[(gn + 1) * HH + 2 * kk], Wh[(gn + 1) * HH + 2 * kk + 1]));
        sw.w1k[kk][ll] = make_ulonglong2(
            pack2(W1N[(2 * ll) * HH + 2 * kk],     W1N[(2 * ll) * HH + 2 * kk + 1]),
            pack2(W1N[(2 * ll + 1) * HH + 2 * kk], W1N[(2 * ll + 1) * HH + 2 * kk + 1]));
        sw.w2k[kk][ll] = make_ulonglong2(
            pack2(W2N[(2 * ll) * HH + 2 * kk],     W2N[(2 * ll) * HH + 2 * kk + 1]),
            pack2(W2N[(2 * ll + 1) * HH + 2 * kk], W2N[(2 * ll + 1) * HH + 2 * kk + 1]));
        if (kk < 3) {
            sw.wir[kk][ll] = make_ulonglong2(
                pack2(Wi[gr * SS + 2 * kk],       Wi[gr * SS + 2 * kk + 1]),
                pack2(Wi[(gr + 1) * SS + 2 * kk], Wi[(gr + 1) * SS + 2 * kk + 1]));
            sw.wiz[kk][ll] = make_ulonglong2(
                pack2(Wi[gz * SS + 2 * kk],       Wi[gz * SS + 2 * kk + 1]),
                pack2(Wi[(gz + 1) * SS + 2 * kk], Wi[(gz + 1) * SS + 2 * kk + 1]));
            sw.win[kk][ll] = make_ulonglong2(
                pack2(Wi[gn * SS + 2 * kk],       Wi[gn * SS + 2 * kk + 1]),
                pack2(Wi[(gn + 1) * SS + 2 * kk], Wi[(gn + 1) * SS + 2 * kk + 1]));
        }
        if (tid < 8) {
            const float* bi = bih + n * GG;
            const float* bh = bhh + n * GG;
            sw.br[tid]  = make_ulonglong2(pack2(bi[2 * tid] + bh[2 * tid], 0.0f),
                                          pack2(bi[2 * tid + 1] + bh[2 * tid + 1], 0.0f));
            sw.bz[tid]  = make_ulonglong2(pack2(bi[16 + 2 * tid] + bh[16 + 2 * tid], 0.0f),
                                          pack2(bi[17 + 2 * tid] + bh[17 + 2 * tid], 0.0f));
            sw.bxn[tid] = make_ulonglong2(pack2(bi[32 + 2 * tid], 0.0f),
                                          pack2(bi[33 + 2 * tid], 0.0f));
            sw.bhn[tid] = make_ulonglong2(pack2(bh[32 + 2 * tid], 0.0f),
                                          pack2(bh[33 + 2 * tid], 0.0f));
            sw.b1v[tid] = make_ulonglong2(pack2(b1[n * HH + 2 * tid], 0.0f),
                                          pack2(b1[n * HH + 2 * tid + 1], 0.0f));
            sw.b2v[tid] = make_ulonglong2(pack2(b2[n * HH + 2 * tid], 0.0f),
                                          pack2(b2[n * HH + 2 * tid + 1], 0.0f));
            sw.w3v[tid] = pack2(W3[n * HH + 2 * tid], W3[n * HH + 2 * tid + 1]);
        }
        if (tid == 0) sw.b3v = b3[n];
    }
    __syncthreads();

    // ---------------- per-group state: 4 sequences ----------------
    const int b0 = qb * 32 + g * 4;
    const int xstride = NN * SS;

    ull hd[4][8];                         // natural h pairs per seq
#pragma unroll
    for (int s = 0; s < 4; s++)
#pragma unroll
        for (int i = 0; i < 8; i++) hd[s][i] = 0ULL;

    const float* xps[4];
#pragma unroll
    for (int s = 0; s < 4; s++)
        xps[s] = x + (long long)(b0 + s) * TT * xstride + n * SS;

    float* op = out + n * (BB * TT) + (b0 + (l & 3)) * TT;
    float ybuf[4];

#pragma unroll 1
    for (int t = 0; t < TT; t++) {
        // --- x loads for 4 seqs (issued early; consumed after h-loop) ---
        ull xv[4][3];
#pragma unroll
        for (int s = 0; s < 4; s++) {
            const float2* px = reinterpret_cast<const float2*>(xps[s]);
            float2 a = __ldg(px), bq = __ldg(px + 1), c = __ldg(px + 2);
            xv[s][0] = pack2(a.x, a.y);
            xv[s][1] = pack2(bq.x, bq.y);
            xv[s][2] = pack2(c.x, c.y);
            xps[s] += xstride;
        }

        // --- K-pair accumulators, bias-folded ---
        ull ra[4][2], za[4][2], xa[4][2], ha[4][2];
        {
            ulonglong2 vbr = sw.br[l], vbz = sw.bz[l], vbx = sw.bxn[l], vbh = sw.bhn[l];
#pragma unroll
            for (int s = 0; s < 4; s++) {
                ra[s][0] = vbr.x; ra[s][1] = vbr.y;
                za[s][0] = vbz.x; za[s][1] = vbz.y;
                xa[s][0] = vbx.x; xa[s][1] = vbx.y;
                ha[s][0] = vbh.x; ha[s][1] = vbh.y;
            }
        }
        // --- h contribution (weights loaded once, reused by 4 seqs) ---
#pragma unroll
        for (int kk = 0; kk < 8; kk++) {
            ulonglong2 wr = sw.whr[kk][l], wz = sw.whz[kk][l], wn = sw.whn[kk][l];
#pragma unroll
            for (int s = 0; s < 4; s++) {
                ull hk = hd[s][kk];
                ra[s][0] = ffma2(hk, wr.x, ra[s][0]); ra[s][1] = ffma2(hk, wr.y, ra[s][1]);
                za[s][0] = ffma2(hk, wz.x, za[s][0]); za[s][1] = ffma2(hk, wz.y, za[s][1]);
                ha[s][0] = ffma2(hk, wn.x, ha[s][0]); ha[s][1] = ffma2(hk, wn.y, ha[s][1]);
            }
        }
        // --- x contribution ---
#pragma unroll
        for (int kk = 0; kk < 3; kk++) {
            ulonglong2 wr = sw.wir[kk][l], wz = sw.wiz[kk][l], wn = sw.win[kk][l];
#pragma unroll
            for (int s = 0; s < 4; s++) {
                ull xk = xv[s][kk];
                ra[s][0] = ffma2(xk, wr.x, ra[s][0]); ra[s][1] = ffma2(xk, wr.y, ra[s][1]);
                za[s][0] = ffma2(xk, wz.x, za[s][0]); za[s][1] = ffma2(xk, wz.y, za[s][1]);
                xa[s][0] = ffma2(xk, wn.x, xa[s][0]); xa[s][1] = ffma2(xk, wn.y, xa[s][1]);
            }
        }

        // --- gates + update of owned h pair ---
        ull own[4];
#pragma unroll
        for (int s = 0; s < 4; s++) {
            float r0 = fsigmoid(hadd2(ra[s][0]));
            float r1 = fsigmoid(hadd2(ra[s][1]));
            float z0 = fsigmoid(hadd2(za[s][0]));
            float z1 = fsigmoid(hadd2(za[s][1]));
            float n0 = ftanh_(fmaf(r0, hadd2(ha[s][0]), hadd2(xa[s][0])));
            float n1 = ftanh_(fmaf(r1, hadd2(ha[s][1]), hadd2(xa[s][1])));
            float2 hold = unpack2(hd[s][l]);
            float h0 = fmaf(z0, hold.x - n0, n0);
            float h1 = fmaf(z1, hold.y - n1, n1);
            own[s] = pack2(h0, h1);
        }
        // --- gather full h (8 pairs from 8 lanes) per seq ---
#pragma unroll
        for (int s = 0; s < 4; s++) {
#pragma unroll
            for (int i = 0; i < 8; i++)
                hd[s][i] = __shfl_sync(0xFFFFFFFFu, own[s], i, 8);
        }

        // --- MLP layer 1 (K-pair over hd) ---
        ull a1[4][2];
        {
            ulonglong2 vb1 = sw.b1v[l];
#pragma unroll
            for (int s = 0; s < 4; s++) { a1[s][0] = vb1.x; a1[s][1] = vb1.y; }
        }
#pragma unroll
        for (int kk = 0; kk < 8; kk++) {
            ulonglong2 w = sw.w1k[kk][l];
#pragma unroll
            for (int s = 0; s < 4; s++) {
                a1[s][0] = ffma2(hd[s][kk], w.x, a1[s][0]);
                a1[s][1] = ffma2(hd[s][kk], w.y, a1[s][1]);
            }
        }
        ull y1own[4];
#pragma unroll
        for (int s = 0; s < 4; s++)
            y1own[s] = pack2(fmaxf(hadd2(a1[s][0]), 0.0f), fmaxf(hadd2(a1[s][1]), 0.0f));

        // --- MLP layer 2: broadcast y1 pairs on the fly ---
        ull a2[4][2];
        {
            ulonglong2 vb2 = sw.b2v[l];
#pragma unroll
            for (int s = 0; s < 4; s++) { a2[s][0] = vb2.x; a2[s][1] = vb2.y; }
        }
#pragma unroll
        for (int src = 0; src < 8; src++) {
            ulonglong2 w = sw.w2k[src][l];
#pragma unroll
            for (int s = 0; s < 4; s++) {
                ull yp = __shfl_sync(0xFFFFFFFFu, y1own[s], src, 8);
                a2[s][0] = ffma2(yp, w.x, a2[s][0]);
                a2[s][1] = ffma2(yp, w.y, a2[s][1]);
            }
        }

        // --- layer 3 + cross-lane reduce ---
        ull w3p = sw.w3v[l];
        float sums[4];
#pragma unroll
        for (int s = 0; s < 4; s++) {
            ull y2p = pack2(fmaxf(hadd2(a2[s][0]), 0.0f), fmaxf(hadd2(a2[s][1]), 0.0f));
            float ps = hadd2(ffma2(y2p, w3p, 0ULL));
            ps += __shfl_xor_sync(0xFFFFFFFFu, ps, 1, 8);
            ps += __shfl_xor_sync(0xFFFFFFFFu, ps, 2, 8);
            ps += __shfl_xor_sync(0xFFFFFFFFu, ps, 4, 8);
            sums[s] = ps;
        }
        const int ls = l & 3;
        float mysum = (ls == 0) ? sums[0] : (ls == 1) ? sums[1] : (ls == 2) ? sums[2] : sums[3];
        ybuf[t & 3] = fmaxf(mysum + sw.b3v, 0.0f);
        if ((t & 3) == 3 && l < 4) {
            *reinterpret_cast<float4*>(op + t - 3) =
                make_float4(ybuf[0], ybuf[1], ybuf[2], ybuf[3]);
        }
    }
}

extern "C" void kernel_launch(void* const* d_in, const int* in_sizes, int n_in,
                              void* d_out, int out_size)
{
    (void)in_sizes; (void)n_in; (void)out_size;
    const float* x   = (const float*)d_in[0];
    const float* Wih = (const float*)d_in[1];
    const float* Whh = (const float*)d_in[2];
    const float* bih = (const float*)d_in[3];
    const float* bhh = (const float*)d_in[4];
    const float* W1  = (const float*)d_in[5];
    const float* b1  = (const float*)d_in[6];
    const float* W2  = (const float*)d_in[7];
    const float* b2  = (const float*)d_in[8];
    const float* W3  = (const float*)d_in[9];
    const float* b3  = (const float*)d_in[10];
    float* out = (float*)d_out;

    actor_fused_kernel<<<NN * 4, 64>>>(x, Wih, Whh, bih, bhh, W1, b1, W2, b2, W3, b3, out);
}